// round 15
// baseline (speedup 1.0000x reference)
#include <cuda_runtime.h>
#include <cuda_bf16.h>
#include <cstddef>
#include <cstdint>

// LIF activation over time axis.
// x: [B=64, T=500, C=1024] fp32; w_input, w_leak: device scalars.
// out: spikes [B, T, C] fp32 (0.0/1.0).
//
// R14 -> R15: cross-replay L2 retention is unobtainable (two sized attempts,
// zero read-traffic delta). Sustained period = 262MB / 46.3us = 5.66 TB/s
// mixed DRAM — the last unrestructured stream is the WRITE path (16B STGs
// via L1/LSU). This round: stage spikes in smem, emit them as TMA bulk s2g
// (10 x 2KB ordered bursts per stage, double-buffered, wait_group recycling).
// Kernel becomes pure smem + TMA in both directions. Read side = R13
// (grid=128, block=160, 5-stage TMA g2s pipeline, evict_last reads).

#define LIF_B 64
#define LIF_T 500
#define LIF_C 1024
#define LIF_HALF 512                     // channels per block
#define LIF_D 10                         // timesteps per stage
#define LIF_NS 5                         // input pipeline stages
#define LIF_NCHUNK (LIF_T / LIF_D)       // 50
#define ROW_BYTES (LIF_HALF * 4)         // 2048
#define STAGE_BYTES (LIF_D * ROW_BYTES)  // 20480
#define OBUFS 2
#define SMEM_BYTES ((LIF_NS + OBUFS) * STAGE_BYTES)   // 100KB in + 40KB out
#define NTHREADS 160

__device__ __forceinline__ uint32_t smem_u32(const void* p) {
    return (uint32_t)__cvta_generic_to_shared(p);
}
__device__ __forceinline__ void mbar_init(uint32_t bar, uint32_t count) {
    asm volatile("mbarrier.init.shared.b64 [%0], %1;" :: "r"(bar), "r"(count) : "memory");
}
__device__ __forceinline__ void mbar_arrive(uint32_t bar) {
    asm volatile("mbarrier.arrive.shared.b64 _, [%0];" :: "r"(bar) : "memory");
}
__device__ __forceinline__ void mbar_expect_tx(uint32_t bar, uint32_t bytes) {
    asm volatile("mbarrier.arrive.expect_tx.shared.b64 _, [%0], %1;"
                 :: "r"(bar), "r"(bytes) : "memory");
}
__device__ __forceinline__ void mbar_wait(uint32_t bar, uint32_t parity) {
    asm volatile(
        "{\n\t"
        ".reg .pred P;\n\t"
        "WAIT_%=:\n\t"
        "mbarrier.try_wait.parity.acquire.cta.shared::cta.b64 P, [%0], %1, 0x989680;\n\t"
        "@!P bra WAIT_%=;\n\t"
        "}"
        :: "r"(bar), "r"(parity) : "memory");
}
__device__ __forceinline__ void bulk_g2s_pol(uint32_t dst, const void* src,
                                             uint32_t bytes, uint32_t bar,
                                             uint64_t pol) {
    asm volatile(
        "cp.async.bulk.shared::cta.global.mbarrier::complete_tx::bytes.L2::cache_hint"
        " [%0], [%1], %2, [%3], %4;"
        :: "r"(dst), "l"(src), "r"(bytes), "r"(bar), "l"(pol) : "memory");
}
__device__ __forceinline__ void bulk_s2g(void* dst, uint32_t src, uint32_t bytes) {
    asm volatile(
        "cp.async.bulk.global.shared::cta.bulk_group [%0], [%1], %2;"
        :: "l"(dst), "r"(src), "r"(bytes) : "memory");
}
#define STORE_COMMIT() asm volatile("cp.async.bulk.commit_group;" ::: "memory")
#define STORE_WAIT(n)  asm volatile("cp.async.bulk.wait_group %0;" :: "n"(n) : "memory")
#define CBAR()         asm volatile("bar.sync 1, 128;" ::: "memory")   // compute warps only

__global__ __launch_bounds__(NTHREADS) void lif_kernel(
    const float* __restrict__ x,
    const float* __restrict__ w_input_p,
    const float* __restrict__ w_leak_p,
    float* __restrict__ out)
{
    extern __shared__ float sdata[];   // [NS stages in][OBUFS stages out] x [D][512]
    __shared__ __align__(8) uint64_t mbar[2 * LIF_NS];

    const int tid = threadIdx.x;
    const uint32_t sbase  = smem_u32(sdata);
    const uint32_t full0  = smem_u32(&mbar[0]);
    const uint32_t empty0 = smem_u32(&mbar[LIF_NS]);
    float* obase = sdata + (size_t)LIF_NS * LIF_D * LIF_HALF;   // output staging

    if (tid == 0) {
        #pragma unroll
        for (int s = 0; s < LIF_NS; s++) {
            mbar_init(full0  + 8u * s, 1);    // producer expect_tx arrival
            mbar_init(empty0 + 8u * s, 128);  // compute threads arrive
        }
    }
    __syncthreads();

    const int blk  = blockIdx.x;       // 0..127
    const int b    = blk >> 1;
    const int half = blk & 1;
    const size_t gbase = (size_t)b * LIF_T * LIF_C + (size_t)half * LIF_HALF;

    if (tid >= 128) {
        // ---------------- producer (one thread drives TMA reads) ----------------
        if (tid != 128) return;
        uint64_t pol;
        asm volatile("createpolicy.fractional.L2::evict_last.b64 %0, 1.0;" : "=l"(pol));
        const char* src0 = (const char*)(x + gbase);
        int ph = 1;
        #pragma unroll 1
        for (int k = 0; k < LIF_NCHUNK; k++) {
            const int s = k % LIF_NS;
            mbar_wait(empty0 + 8u * s, (uint32_t)ph);
            mbar_expect_tx(full0 + 8u * s, STAGE_BYTES);
            const char* src = src0 + (size_t)k * LIF_D * LIF_C * 4;
            #pragma unroll
            for (int j = 0; j < LIF_D; j++)
                bulk_g2s_pol(sbase + (uint32_t)(s * LIF_D + j) * ROW_BYTES,
                             src + (size_t)j * LIF_C * 4,
                             ROW_BYTES, full0 + 8u * s, pol);
            if (s == LIF_NS - 1) ph ^= 1;
        }
        return;
    }

    // ---------------- compute threads (128, float4 each) ----------------
    const float wi   = *w_input_p;
    const float keep = 1.0f - *w_leak_p;

    float* orow = out + gbase;
    float Vm0 = 0.0f, Vm1 = 0.0f, Vm2 = 0.0f, Vm3 = 0.0f;
    int ph = 0;

    #pragma unroll 1
    for (int k = 0; k < LIF_NCHUNK; k++) {
        const int s = k % LIF_NS;
        const int ob = k & (OBUFS - 1);

        // Recycle output buffer: ensure chunk k-2's stores completed.
        if (tid == 0 && k >= OBUFS) STORE_WAIT(1);
        CBAR();                         // buffer free for everyone

        mbar_wait(full0 + 8u * s, (uint32_t)ph);

        const float4* srow = (const float4*)(sdata + (size_t)s * LIF_D * LIF_HALF) + tid;
        float4* drow = (float4*)(obase + (size_t)ob * LIF_D * LIF_HALF) + tid;
        #pragma unroll
        for (int j = 0; j < LIF_D; j++) {
            const float4 xv = srow[(size_t)j * (LIF_HALF / 4)];
            const float vk0 = (Vm0 < 1.0f) ? Vm0 : 0.0f;   // Vm * step(1-Vm)
            const float vk1 = (Vm1 < 1.0f) ? Vm1 : 0.0f;
            const float vk2 = (Vm2 < 1.0f) ? Vm2 : 0.0f;
            const float vk3 = (Vm3 < 1.0f) ? Vm3 : 0.0f;
            Vm0 = fmaxf(fmaf(keep, vk0, wi * xv.x), 0.0f);
            Vm1 = fmaxf(fmaf(keep, vk1, wi * xv.y), 0.0f);
            Vm2 = fmaxf(fmaf(keep, vk2, wi * xv.z), 0.0f);
            Vm3 = fmaxf(fmaf(keep, vk3, wi * xv.w), 0.0f);
            float4 sp;
            sp.x = (Vm0 > 1.0f) ? 1.0f : 0.0f;
            sp.y = (Vm1 > 1.0f) ? 1.0f : 0.0f;
            sp.z = (Vm2 > 1.0f) ? 1.0f : 0.0f;
            sp.w = (Vm3 > 1.0f) ? 1.0f : 0.0f;
            drow[(size_t)j * (LIF_HALF / 4)] = sp;          // STS (smem staging)
        }

        mbar_arrive(empty0 + 8u * s);   // input stage consumed
        CBAR();                         // all spike STS visible

        if (tid == 0) {
            // Order generic-proxy STS before async-proxy bulk reads of smem.
            asm volatile("fence.proxy.async.shared::cta;" ::: "memory");
            const uint32_t osrc = smem_u32(obase + (size_t)ob * LIF_D * LIF_HALF);
            float* dst = orow + (size_t)k * LIF_D * LIF_C;
            #pragma unroll
            for (int j = 0; j < LIF_D; j++)
                bulk_s2g(dst + (size_t)j * LIF_C, osrc + (uint32_t)j * ROW_BYTES, ROW_BYTES);
            STORE_COMMIT();
        }

        if (s == LIF_NS - 1) ph ^= 1;
    }

    // Drain pending store groups before exit.
    if (tid == 0) STORE_WAIT(0);
}

extern "C" void kernel_launch(void* const* d_in, const int* in_sizes, int n_in,
                              void* d_out, int out_size) {
    const float* x        = (const float*)d_in[0];
    const float* w_input  = (const float*)d_in[1];
    const float* w_leak   = (const float*)d_in[2];
    float* out            = (float*)d_out;

    cudaFuncSetAttribute(lif_kernel,
                         cudaFuncAttributeMaxDynamicSharedMemorySize, SMEM_BYTES);

    lif_kernel<<<LIF_B * 2, NTHREADS, SMEM_BYTES>>>(x, w_input, w_leak, out);
}

// round 16
// speedup vs baseline: 1.1515x; 1.1515x over previous
#include <cuda_runtime.h>
#include <cuda_bf16.h>
#include <cstddef>
#include <cstdint>

// LIF activation over time axis.
// x: [B=64, T=500, C=1024] fp32; w_input, w_leak: device scalars.
// out: spikes [B, T, C] fp32 (0.0/1.0).
//
// R15 -> R16: TMA-store staging serialized the pipeline (barriers coupling
// compute warps) -> revert to R13, the best structure (46.30us). Evidence
// across 15 rounds says we sit at the sustained mixed R+W DRAM ceiling
// (~5.7-5.8 TB/s); the one untried monotone knob on the proven shape is
// pipeline DEPTH: 5 -> 9 stages (184KB dyn smem, 1 CTA/SM so smem is free).
// Producer runs 8 stages (160KB) ahead, covering the moments where compute
// caught the prefetch horizon.

#define LIF_B 64
#define LIF_T 500
#define LIF_C 1024
#define LIF_HALF 512                     // channels per block
#define LIF_D 10                         // timesteps per stage
#define LIF_NS 9                         // pipeline stages (was 5)
#define LIF_NCHUNK (LIF_T / LIF_D)       // 50
#define ROW_BYTES (LIF_HALF * 4)         // 2048
#define STAGE_BYTES (LIF_D * ROW_BYTES)  // 20480
#define SMEM_BYTES (LIF_NS * STAGE_BYTES)  // 184320
#define NTHREADS 160

__device__ __forceinline__ uint32_t smem_u32(const void* p) {
    return (uint32_t)__cvta_generic_to_shared(p);
}
__device__ __forceinline__ void mbar_init(uint32_t bar, uint32_t count) {
    asm volatile("mbarrier.init.shared.b64 [%0], %1;" :: "r"(bar), "r"(count) : "memory");
}
__device__ __forceinline__ void mbar_arrive(uint32_t bar) {
    asm volatile("mbarrier.arrive.shared.b64 _, [%0];" :: "r"(bar) : "memory");
}
__device__ __forceinline__ void mbar_expect_tx(uint32_t bar, uint32_t bytes) {
    asm volatile("mbarrier.arrive.expect_tx.shared.b64 _, [%0], %1;"
                 :: "r"(bar), "r"(bytes) : "memory");
}
__device__ __forceinline__ void mbar_wait(uint32_t bar, uint32_t parity) {
    asm volatile(
        "{\n\t"
        ".reg .pred P;\n\t"
        "WAIT_%=:\n\t"
        "mbarrier.try_wait.parity.acquire.cta.shared::cta.b64 P, [%0], %1, 0x989680;\n\t"
        "@!P bra WAIT_%=;\n\t"
        "}"
        :: "r"(bar), "r"(parity) : "memory");
}
__device__ __forceinline__ void bulk_g2s_pol(uint32_t dst, const void* src,
                                             uint32_t bytes, uint32_t bar,
                                             uint64_t pol) {
    asm volatile(
        "cp.async.bulk.shared::cta.global.mbarrier::complete_tx::bytes.L2::cache_hint"
        " [%0], [%1], %2, [%3], %4;"
        :: "r"(dst), "l"(src), "r"(bytes), "r"(bar), "l"(pol) : "memory");
}

__global__ __launch_bounds__(NTHREADS) void lif_kernel(
    const float* __restrict__ x,
    const float* __restrict__ w_input_p,
    const float* __restrict__ w_leak_p,
    float* __restrict__ out)
{
    extern __shared__ float sdata[];                    // LIF_NS stages of [D][512] floats
    __shared__ __align__(8) uint64_t mbar[2 * LIF_NS];  // full[0..NS), empty[0..NS)

    const int tid = threadIdx.x;
    const uint32_t sbase  = smem_u32(sdata);
    const uint32_t full0  = smem_u32(&mbar[0]);
    const uint32_t empty0 = smem_u32(&mbar[LIF_NS]);

    if (tid == 0) {
        #pragma unroll
        for (int s = 0; s < LIF_NS; s++) {
            mbar_init(full0  + 8u * s, 1);    // producer expect_tx arrival
            mbar_init(empty0 + 8u * s, 128);  // all compute threads arrive
        }
    }
    __syncthreads();

    const int blk  = blockIdx.x;       // 0..127
    const int b    = blk >> 1;
    const int half = blk & 1;
    const size_t gbase = (size_t)b * LIF_T * LIF_C + (size_t)half * LIF_HALF;

    if (tid >= 128) {
        // ---------------- producer (one thread drives TMA) ----------------
        if (tid != 128) return;
        uint64_t pol;
        asm volatile("createpolicy.fractional.L2::evict_last.b64 %0, 1.0;" : "=l"(pol));
        const char* src0 = (const char*)(x + gbase);
        int ph = 1;                    // empty barriers: first pass must not block
        #pragma unroll 1
        for (int k = 0; k < LIF_NCHUNK; k++) {
            const int s = k % LIF_NS;
            mbar_wait(empty0 + 8u * s, (uint32_t)ph);
            mbar_expect_tx(full0 + 8u * s, STAGE_BYTES);
            const char* src = src0 + (size_t)k * LIF_D * LIF_C * 4;
            #pragma unroll
            for (int j = 0; j < LIF_D; j++)
                bulk_g2s_pol(sbase + (uint32_t)(s * LIF_D + j) * ROW_BYTES,
                             src + (size_t)j * LIF_C * 4,
                             ROW_BYTES, full0 + 8u * s, pol);
            if (s == LIF_NS - 1) ph ^= 1;
        }
        return;
    }

    // ---------------- compute threads (128, float4 each) ----------------
    const float wi   = *w_input_p;
    const float keep = 1.0f - *w_leak_p;

    float* orow = out + gbase;
    float Vm0 = 0.0f, Vm1 = 0.0f, Vm2 = 0.0f, Vm3 = 0.0f;
    int ph = 0;

    #pragma unroll 1
    for (int k = 0; k < LIF_NCHUNK; k++) {
        const int s = k % LIF_NS;
        mbar_wait(full0 + 8u * s, (uint32_t)ph);

        const float4* srow = (const float4*)(sdata + (size_t)s * LIF_D * LIF_HALF) + tid;
        #pragma unroll
        for (int j = 0; j < LIF_D; j++) {
            const float4 xv = srow[(size_t)j * (LIF_HALF / 4)];
            const float vk0 = (Vm0 < 1.0f) ? Vm0 : 0.0f;   // Vm * step(1-Vm)
            const float vk1 = (Vm1 < 1.0f) ? Vm1 : 0.0f;
            const float vk2 = (Vm2 < 1.0f) ? Vm2 : 0.0f;
            const float vk3 = (Vm3 < 1.0f) ? Vm3 : 0.0f;
            Vm0 = fmaxf(fmaf(keep, vk0, wi * xv.x), 0.0f);
            Vm1 = fmaxf(fmaf(keep, vk1, wi * xv.y), 0.0f);
            Vm2 = fmaxf(fmaf(keep, vk2, wi * xv.z), 0.0f);
            Vm3 = fmaxf(fmaf(keep, vk3, wi * xv.w), 0.0f);
            float4 sp;
            sp.x = (Vm0 > 1.0f) ? 1.0f : 0.0f;
            sp.y = (Vm1 > 1.0f) ? 1.0f : 0.0f;
            sp.z = (Vm2 > 1.0f) ? 1.0f : 0.0f;
            sp.w = (Vm3 > 1.0f) ? 1.0f : 0.0f;
            __stcs((float4*)(orow + (size_t)(k * LIF_D + j) * LIF_C + tid * 4), sp);
        }

        mbar_arrive(empty0 + 8u * s);
        if (s == LIF_NS - 1) ph ^= 1;
    }
}

extern "C" void kernel_launch(void* const* d_in, const int* in_sizes, int n_in,
                              void* d_out, int out_size) {
    const float* x        = (const float*)d_in[0];
    const float* w_input  = (const float*)d_in[1];
    const float* w_leak   = (const float*)d_in[2];
    float* out            = (float*)d_out;

    cudaFuncSetAttribute(lif_kernel,
                         cudaFuncAttributeMaxDynamicSharedMemorySize, SMEM_BYTES);

    lif_kernel<<<LIF_B * 2, NTHREADS, SMEM_BYTES>>>(x, w_input, w_leak, out);
}